// round 9
// baseline (speedup 1.0000x reference)
#include <cuda_runtime.h>
#include <cstdint>

#define B_TOK 65536
#define KD    512
#define NC    101
#define NE    8
#define NH    256
#define N1    2048

#define BM      128
#define BK      32
#define THREADS 256
#define SLAB_ST 36          // floats per row in As/Bs slabs (32 + 4 pad)
#define H_ST    260         // floats per row in Hs (256 + 4 pad)

// ---------------- device scratch ----------------
__device__ float g_Xc [B_TOK * KD];   // X pre-converted to tf32 (128 MiB)
__device__ float g_W1T[N1 * KD];      // [n=e*256+h][d], tf32
__device__ float g_W2T[128 * N1];     // [c(pad 128)][e*256+h], tf32
__device__ float g_G  [B_TOK * NE];   // gates (fp32)

// ---------------- helpers ----------------
__device__ __forceinline__ uint32_t smem_u32(const void* p) {
    uint32_t a;
    asm("{ .reg .u64 t; cvta.to.shared.u64 t, %1; cvt.u32.u64 %0, t; }" : "=r"(a) : "l"(p));
    return a;
}
__device__ __forceinline__ float to_tf32(float x) {
    uint32_t u; asm("cvt.rna.tf32.f32 %0, %1;" : "=r"(u) : "f"(x));
    return __uint_as_float(u);
}
__device__ __forceinline__ void cpa16(uint32_t s, const void* g) {
    asm volatile("cp.async.cg.shared.global [%0], [%1], 16;" :: "r"(s), "l"(g));
}
#define CP_COMMIT() asm volatile("cp.async.commit_group;" ::: "memory")
#define CP_WAIT0()  asm volatile("cp.async.wait_group 0;" ::: "memory")

__device__ __forceinline__ void mma_tf32(float* d, const float* a, const float* b) {
    asm volatile(
        "mma.sync.aligned.m16n8k8.row.col.f32.tf32.tf32.f32 "
        "{%0,%1,%2,%3}, {%4,%5,%6,%7}, {%8,%9}, {%0,%1,%2,%3};"
        : "+f"(d[0]), "+f"(d[1]), "+f"(d[2]), "+f"(d[3])
        : "r"(__float_as_uint(a[0])), "r"(__float_as_uint(a[1])),
          "r"(__float_as_uint(a[2])), "r"(__float_as_uint(a[3])),
          "r"(__float_as_uint(b[0])), "r"(__float_as_uint(b[1])));
}

// ---------------- prep kernels ----------------
__global__ void k_cvtx(const float* __restrict__ X) {
    int i = blockIdx.x * 256 + threadIdx.x;      // over 8,388,608 float4
    const float4* src = reinterpret_cast<const float4*>(X);
    float4 v = src[i];
    v.x = to_tf32(v.x); v.y = to_tf32(v.y); v.z = to_tf32(v.z); v.w = to_tf32(v.w);
    reinterpret_cast<float4*>(g_Xc)[i] = v;
}

__global__ void k_tw1(const float* __restrict__ W1) {
    // W1 [E][D][H] -> g_W1T[e*NH+h][d]
    __shared__ float tile[32][33];
    int e = blockIdx.z, d0 = blockIdx.y * 32, h0 = blockIdx.x * 32;
    int tx = threadIdx.x, ty = threadIdx.y;
    #pragma unroll
    for (int r = 0; r < 32; r += 8)
        tile[ty + r][tx] = W1[((size_t)e * KD + d0 + ty + r) * NH + h0 + tx];
    __syncthreads();
    #pragma unroll
    for (int r = 0; r < 32; r += 8)
        g_W1T[((size_t)e * NH + h0 + ty + r) * KD + d0 + tx] = to_tf32(tile[tx][ty + r]);
}

__global__ void k_tw2(const float* __restrict__ W2) {
    // W2 [E][H][C] -> g_W2T[c][e*NH+h], c padded to 128
    int idx = blockIdx.x * 256 + threadIdx.x;    // over 128*2048
    int eh = idx & (N1 - 1);
    int c  = idx >> 11;
    g_W2T[(size_t)c * N1 + eh] = (c < NC) ? to_tf32(W2[(size_t)eh * NC + c]) : 0.0f;
}

__global__ void k_gates(const float* __restrict__ X, const float* __restrict__ Wg,
                        const float* __restrict__ bg) {
    int wg   = (blockIdx.x * blockDim.x + threadIdx.x) >> 5;
    int lane = threadIdx.x & 31;
    if (wg >= B_TOK) return;
    const float* xr = X + (size_t)wg * KD;
    float a[NE];
    #pragma unroll
    for (int e = 0; e < NE; e++) a[e] = 0.f;
    for (int d = lane; d < KD; d += 32) {
        float xv = xr[d];
        const float4* w = reinterpret_cast<const float4*>(Wg + (size_t)d * NE);
        float4 u = w[0], v = w[1];
        a[0] += xv * u.x; a[1] += xv * u.y; a[2] += xv * u.z; a[3] += xv * u.w;
        a[4] += xv * v.x; a[5] += xv * v.y; a[6] += xv * v.z; a[7] += xv * v.w;
    }
    #pragma unroll
    for (int e = 0; e < NE; e++)
        #pragma unroll
        for (int off = 16; off > 0; off >>= 1)
            a[e] += __shfl_xor_sync(0xFFFFFFFFu, a[e], off);
    if (lane == 0) {
        float m = -1e30f;
        #pragma unroll
        for (int e = 0; e < NE; e++) { a[e] += bg[e]; m = fmaxf(m, a[e]); }
        float s = 0.f;
        #pragma unroll
        for (int e = 0; e < NE; e++) { a[e] = __expf(a[e] - m); s += a[e]; }
        float inv = 1.0f / s;
        #pragma unroll
        for (int e = 0; e < NE; e++) g_G[(size_t)wg * NE + e] = a[e] * inv;
    }
}

// ---------------- smem layout (floats) ----------------
// As[2][128][36]  = 9216
// Bs[2][128][36]  = 9216
// Hs[128][260]    = 33280
// b1s[2048], b2s[128*8], gs[128*8]
#define OFF_AS   0
#define OFF_BS   (2 * 128 * SLAB_ST)
#define OFF_HS   (OFF_BS + 2 * 128 * SLAB_ST)
#define OFF_B1   (OFF_HS + 128 * H_ST)
#define OFF_B2   (OFF_B1 + N1)
#define OFF_GS   (OFF_B2 + 128 * NE)
#define SMEM_F   (OFF_GS + 128 * NE)           // 55808 floats = 223232 B

__device__ __forceinline__ void ld_slab(uint32_t dst, const float* src, int stride, int tid) {
    #pragma unroll
    for (int it = 0; it < 4; it++) {
        int id = tid + it * THREADS;            // 0..1023
        int r = id >> 3, j = id & 7;
        cpa16(dst + (uint32_t)(r * (SLAB_ST * 4) + j * 16),
              src + (size_t)r * stride + j * 4);
    }
}

// ---------------- main fused kernel ----------------
__global__ void __launch_bounds__(THREADS, 1)
k_moe(const float* __restrict__ b1, const float* __restrict__ b2,
      float* __restrict__ Out)
{
    extern __shared__ float sm[];
    float* As  = sm + OFF_AS;
    float* Bs  = sm + OFF_BS;
    float* Hs  = sm + OFF_HS;
    float* b1s = sm + OFF_B1;
    float* b2s = sm + OFF_B2;
    float* gs  = sm + OFF_GS;

    const int tid  = threadIdx.x;
    const int wid  = tid >> 5, lane = tid & 31;
    const int g    = lane >> 2, c = lane & 3;
    const int wm   = wid & 1, wn = wid >> 1;     // 2 x 4 warp grid
    const int m0w  = wm * 64, n0w = wn * 32;
    const int bm0  = blockIdx.x * BM;

    const uint32_t asu = smem_u32(As);
    const uint32_t bsu = smem_u32(Bs);
    const uint32_t abuf[2] = { asu, asu + 128u * SLAB_ST * 4u };
    const uint32_t bbuf[2] = { bsu, bsu + 128u * SLAB_ST * 4u };
    const float* Af[2] = { As, As + 128 * SLAB_ST };
    const float* Bf[2] = { Bs, Bs + 128 * SLAB_ST };

    // stage biases + gates
    for (int i = tid; i < N1; i += THREADS) b1s[i] = b1[i];
    for (int i = tid; i < 128 * NE; i += THREADS) {
        int cc = i >> 3, e = i & 7;
        b2s[i] = (cc < NC) ? b2[(size_t)e * NC + cc] : 0.0f;
        gs[i]  = g_G[(size_t)(bm0 + (i >> 3)) * NE + e];
    }
    __syncthreads();

    float acc2[4][4][4];
    #pragma unroll
    for (int i = 0; i < 4; i++)
        #pragma unroll
        for (int j = 0; j < 4; j++)
            #pragma unroll
            for (int q = 0; q < 4; q++) acc2[i][j][q] = 0.0f;

    for (int ch = 0; ch < NE; ch++) {
        // ================= GEMM1 in two n-halves of 128 =================
        #pragma unroll 1
        for (int nh = 0; nh < 2; nh++) {
            float acc1[4][4][4];
            #pragma unroll
            for (int i = 0; i < 4; i++)
                #pragma unroll
                for (int j = 0; j < 4; j++)
                    #pragma unroll
                    for (int q = 0; q < 4; q++) acc1[i][j][q] = 0.0f;

            const float* Xb  = g_Xc  + (size_t)bm0 * KD;
            const float* W1b = g_W1T + (size_t)(ch * NH + nh * 128) * KD;

            ld_slab(abuf[0], Xb, KD, tid);
            ld_slab(bbuf[0], W1b, KD, tid);
            CP_COMMIT();

            #pragma unroll 1
            for (int kb = 0; kb < KD / BK; kb++) {
                int cur = kb & 1;
                CP_WAIT0();
                __syncthreads();
                if (kb + 1 < KD / BK) {
                    ld_slab(abuf[cur ^ 1], Xb  + (kb + 1) * BK, KD, tid);
                    ld_slab(bbuf[cur ^ 1], W1b + (kb + 1) * BK, KD, tid);
                    CP_COMMIT();
                }
                const float* Ab = Af[cur];
                const float* Bb = Bf[cur];
                #pragma unroll
                for (int kk = 0; kk < 4; kk++) {
                    float a[4][4], b[4][2];
                    #pragma unroll
                    for (int mf = 0; mf < 4; mf++) {
                        const float* p = Ab + (m0w + mf * 16 + g) * SLAB_ST + kk * 8 + c;
                        a[mf][0] = p[0];
                        a[mf][1] = p[8 * SLAB_ST];
                        a[mf][2] = p[4];
                        a[mf][3] = p[8 * SLAB_ST + 4];
                    }
                    #pragma unroll
                    for (int nf = 0; nf < 4; nf++) {
                        const float* p = Bb + (n0w + nf * 8 + g) * SLAB_ST + kk * 8 + c;
                        b[nf][0] = p[0];
                        b[nf][1] = p[4];
                    }
                    #pragma unroll
                    for (int mf = 0; mf < 4; mf++)
                        #pragma unroll
                        for (int nf = 0; nf < 4; nf++)
                            mma_tf32(acc1[mf][nf], a[mf], b[nf]);
                }
            }

            // ---- epilogue 1: H = tf32(relu(acc + b1) * gate) -> Hs ----
            #pragma unroll
            for (int mf = 0; mf < 4; mf++) {
                int r0 = m0w + mf * 16 + g;
                float g0 = gs[r0 * NE + ch];
                float g1 = gs[(r0 + 8) * NE + ch];
                #pragma unroll
                for (int nf = 0; nf < 4; nf++) {
                    int col  = n0w + nf * 8 + 2 * c;
                    int ncol = nh * 128 + col;
                    const float* bb = b1s + ch * NH + ncol;
                    float h00 = to_tf32(fmaxf(acc1[mf][nf][0] + bb[0], 0.f) * g0);
                    float h01 = to_tf32(fmaxf(acc1[mf][nf][1] + bb[1], 0.f) * g0);
                    float h10 = to_tf32(fmaxf(acc1[mf][nf][2] + bb[0], 0.f) * g1);
                    float h11 = to_tf32(fmaxf(acc1[mf][nf][3] + bb[1], 0.f) * g1);
                    *reinterpret_cast<float2*>(Hs + r0 * H_ST + ncol)       = make_float2(h00, h01);
                    *reinterpret_cast<float2*>(Hs + (r0 + 8) * H_ST + ncol) = make_float2(h10, h11);
                }
            }
        }
        __syncthreads();   // Hs complete before GEMM2 reads it

        // ================= GEMM2: acc2 += H @ W2T^T  (K = 256) =================
        const float* W2b = g_W2T + ch * NH;
        ld_slab(bbuf[0], W2b, N1, tid);
        CP_COMMIT();
        #pragma unroll 1
        for (int kb = 0; kb < NH / BK; kb++) {
            int cur = kb & 1;
            CP_WAIT0();
            __syncthreads();
            if (kb + 1 < NH / BK) {
                ld_slab(bbuf[cur ^ 1], W2b + (kb + 1) * BK, N1, tid);
                CP_COMMIT();
            }
            const float* Bb = Bf[cur];
            #pragma unroll
            for (int kk = 0; kk < 4; kk++) {
                float a[4][4], b[4][2];
                #pragma unroll
                for (int mf = 0; mf < 4; mf++) {
                    const float* p = Hs + (m0w + mf * 16 + g) * H_ST + kb * BK + kk * 8 + c;
                    a[mf][0] = p[0];
                    a[mf][1] = p[8 * H_ST];
                    a[mf][2] = p[4];
                    a[mf][3] = p[8 * H_ST + 4];
                }
                #pragma unroll
                for (int nf = 0; nf < 4; nf++) {
                    const float* p = Bb + (n0w + nf * 8 + g) * SLAB_ST + kk * 8 + c;
                    b[nf][0] = p[0];
                    b[nf][1] = p[4];
                }
                #pragma unroll
                for (int mf = 0; mf < 4; mf++)
                    #pragma unroll
                    for (int nf = 0; nf < 4; nf++)
                        mma_tf32(acc2[mf][nf], a[mf], b[nf]);
            }
        }
        __syncthreads();   // Bs free + Hs free before next expert reuses them
    }

    // ================= final epilogue: out = acc2 + G @ b2 =================
    #pragma unroll
    for (int mf = 0; mf < 4; mf++) {
        int r0 = m0w + mf * 16 + g;
        #pragma unroll
        for (int nf = 0; nf < 4; nf++) {
            int col = n0w + nf * 8 + 2 * c;
            #pragma unroll
            for (int q = 0; q < 4; q++) {
                int r  = r0 + ((q >> 1) ? 8 : 0);
                int cc = col + (q & 1);
                float v = acc2[mf][nf][q];
                const float* gv = gs  + r * NE;
                const float* bv = b2s + cc * NE;
                #pragma unroll
                for (int e = 0; e < NE; e++) v += gv[e] * bv[e];
                if (cc < NC) Out[(size_t)(bm0 + r) * NC + cc] = v;
            }
        }
    }
}

// ---------------- launch ----------------
extern "C" void kernel_launch(void* const* d_in, const int* in_sizes, int n_in,
                              void* d_out, int out_size) {
    const float* x  = (const float*)d_in[0];
    const float* W1 = (const float*)d_in[1];
    const float* b1 = (const float*)d_in[2];
    const float* W2 = (const float*)d_in[3];
    const float* b2 = (const float*)d_in[4];
    const float* Wg = (const float*)d_in[5];
    const float* bg = (const float*)d_in[6];
    float* out = (float*)d_out;

    k_cvtx <<<(B_TOK * KD / 4) / 256, 256>>>(x);
    k_tw1  <<<dim3(NH / 32, KD / 32, NE), dim3(32, 8)>>>(W1);
    k_tw2  <<<(128 * N1) / 256, 256>>>(W2);
    k_gates<<<B_TOK / 8, 256>>>(x, Wg, bg);

    cudaFuncSetAttribute(k_moe, cudaFuncAttributeMaxDynamicSharedMemorySize, SMEM_F * 4);
    k_moe<<<B_TOK / BM, THREADS, SMEM_F * 4>>>(b1, b2, out);
}

// round 10
// speedup vs baseline: 2.4070x; 2.4070x over previous
#include <cuda_runtime.h>
#include <cuda_fp16.h>
#include <cstdint>

#define B_TOK 65536
#define KD    512
#define NC    101
#define NE    8
#define NH    256
#define N1    2048

#define BM      128
#define THREADS 512

// strides in halves (padded for conflict-free ldmatrix)
#define X_ST  520    // 1040 B
#define B_ST  72     // 144 B  (BK=64 slab)
#define H_ST  136    // 272 B  (128-col half-tile)

// ---------------- device scratch ----------------
__device__ __half g_Xh [B_TOK * KD];   // X in fp16 (64 MB)
__device__ __half g_W1T[N1 * KD];      // [n=e*256+h][d] fp16
__device__ __half g_W2T[128 * N1];     // [c(pad128)][e*256+h] fp16
__device__ float  g_G  [B_TOK * NE];   // gates fp32

// ---------------- helpers ----------------
__device__ __forceinline__ uint32_t smem_u32(const void* p) {
    uint32_t a;
    asm("{ .reg .u64 t; cvta.to.shared.u64 t, %1; cvt.u32.u64 %0, t; }" : "=r"(a) : "l"(p));
    return a;
}
__device__ __forceinline__ void cpa16(uint32_t s, const void* g) {
    asm volatile("cp.async.cg.shared.global [%0], [%1], 16;" :: "r"(s), "l"(g));
}
#define CP_COMMIT() asm volatile("cp.async.commit_group;" ::: "memory")
#define CP_WAIT0()  asm volatile("cp.async.wait_group 0;" ::: "memory")

__device__ __forceinline__ void ldm4(uint32_t* r, uint32_t addr) {
    asm volatile("ldmatrix.sync.aligned.m8n8.x4.shared.b16 {%0,%1,%2,%3}, [%4];"
                 : "=r"(r[0]), "=r"(r[1]), "=r"(r[2]), "=r"(r[3]) : "r"(addr));
}
__device__ __forceinline__ void mma_f16(float* d, const uint32_t* a, const uint32_t* b) {
    asm volatile(
        "mma.sync.aligned.m16n8k16.row.col.f32.f16.f16.f32 "
        "{%0,%1,%2,%3}, {%4,%5,%6,%7}, {%8,%9}, {%0,%1,%2,%3};"
        : "+f"(d[0]), "+f"(d[1]), "+f"(d[2]), "+f"(d[3])
        : "r"(a[0]), "r"(a[1]), "r"(a[2]), "r"(a[3]), "r"(b[0]), "r"(b[1]));
}

// ---------------- prep kernels ----------------
__global__ void k_tw1(const float* __restrict__ W1) {
    // W1 [E][D][H] fp32 -> g_W1T[e*NH+h][d] fp16
    __shared__ float tile[32][33];
    int e = blockIdx.z, d0 = blockIdx.y * 32, h0 = blockIdx.x * 32;
    int tx = threadIdx.x, ty = threadIdx.y;
    #pragma unroll
    for (int r = 0; r < 32; r += 8)
        tile[ty + r][tx] = W1[((size_t)e * KD + d0 + ty + r) * NH + h0 + tx];
    __syncthreads();
    #pragma unroll
    for (int r = 0; r < 32; r += 8)
        g_W1T[((size_t)e * NH + h0 + ty + r) * KD + d0 + tx] =
            __float2half_rn(tile[tx][ty + r]);
}

__global__ void k_tw2(const float* __restrict__ W2) {
    // W2 [E][H][C] -> g_W2T[c][e*256+h] fp16, c padded to 128
    int idx = blockIdx.x * 256 + threadIdx.x;    // over 128*2048
    int eh = idx & (N1 - 1);
    int c  = idx >> 11;
    g_W2T[(size_t)c * N1 + eh] =
        (c < NC) ? __float2half_rn(W2[(size_t)eh * NC + c]) : __half(0.0f);
}

__global__ void k_gates(const float* __restrict__ X, const float* __restrict__ Wg,
                        const float* __restrict__ bg) {
    // gates + write X as fp16
    int wg   = (blockIdx.x * blockDim.x + threadIdx.x) >> 5;
    int lane = threadIdx.x & 31;
    if (wg >= B_TOK) return;
    const float* xr = X + (size_t)wg * KD;
    __half* xh = g_Xh + (size_t)wg * KD;
    float a[NE];
    #pragma unroll
    for (int e = 0; e < NE; e++) a[e] = 0.f;
    for (int d = lane; d < KD; d += 32) {
        float xv = xr[d];
        xh[d] = __float2half_rn(xv);
        const float4* w = reinterpret_cast<const float4*>(Wg + (size_t)d * NE);
        float4 u = w[0], v = w[1];
        a[0] += xv * u.x; a[1] += xv * u.y; a[2] += xv * u.z; a[3] += xv * u.w;
        a[4] += xv * v.x; a[5] += xv * v.y; a[6] += xv * v.z; a[7] += xv * v.w;
    }
    #pragma unroll
    for (int e = 0; e < NE; e++)
        #pragma unroll
        for (int off = 16; off > 0; off >>= 1)
            a[e] += __shfl_xor_sync(0xFFFFFFFFu, a[e], off);
    if (lane == 0) {
        float m = -1e30f;
        #pragma unroll
        for (int e = 0; e < NE; e++) { a[e] += bg[e]; m = fmaxf(m, a[e]); }
        float s = 0.f;
        #pragma unroll
        for (int e = 0; e < NE; e++) { a[e] = __expf(a[e] - m); s += a[e]; }
        float inv = 1.0f / s;
        #pragma unroll
        for (int e = 0; e < NE; e++) g_G[(size_t)wg * NE + e] = a[e] * inv;
    }
}

// ---------------- smem layout (bytes) ----------------
#define OFF_XS  0
#define OFF_BS  (128 * X_ST * 2)                 // 133120
#define OFF_HS  (OFF_BS + 2 * 128 * B_ST * 2)    // 169984
#define OFF_B1  (OFF_HS + 128 * H_ST * 2)        // 204800
#define OFF_B2  (OFF_B1 + N1 * 4)                // 212992
#define OFF_GS  (OFF_B2 + 128 * NE * 4)          // 217088
#define SM_TOT  (OFF_GS + 128 * NE * 4)          // 221184

// B-slab loader: 128 rows x 64 halves (128 B/row), stride B_ST
__device__ __forceinline__ void ld_slabB(uint32_t dst, const __half* src,
                                         int stride, int tid) {
    #pragma unroll
    for (int it = 0; it < 2; it++) {
        int id = tid + it * THREADS;      // 0..1023
        int r = id >> 3, j = id & 7;
        cpa16(dst + (uint32_t)(r * (B_ST * 2) + j * 16),
              src + (size_t)r * stride + j * 8);
    }
}

// ---------------- main fused kernel ----------------
__global__ void __launch_bounds__(THREADS, 1)
k_moe(const float* __restrict__ b1, const float* __restrict__ b2,
      float* __restrict__ Out)
{
    extern __shared__ char smem[];
    __half* Hs  = (__half*)(smem + OFF_HS);
    float*  b1s = (float*)(smem + OFF_B1);
    float*  b2s = (float*)(smem + OFF_B2);
    float*  gs  = (float*)(smem + OFF_GS);

    const int tid  = threadIdx.x;
    const int wid  = tid >> 5, lane = tid & 31;
    const int wm   = wid & 3, wn = wid >> 2;      // 4 x 4 warp grid
    const int m0w  = wm * 32, n0w = wn * 32;
    const int g    = lane >> 2, t = lane & 3;
    const int bm0  = blockIdx.x * BM;

    const uint32_t xs_u = smem_u32(smem + OFF_XS);
    const uint32_t bs_u = smem_u32(smem + OFF_BS);
    const uint32_t hs_u = smem_u32(smem + OFF_HS);
    const uint32_t bbuf[2] = { bs_u, bs_u + 128u * B_ST * 2u };

    // ---- load resident X tile (128 x 512 fp16) ----
    {
        const __half* Xg = g_Xh + (size_t)bm0 * KD;
        #pragma unroll
        for (int it = 0; it < 16; it++) {
            int id = tid + it * THREADS;          // 0..8191
            int r = id >> 6, j = id & 63;
            cpa16(xs_u + (uint32_t)(r * (X_ST * 2) + j * 16),
                  Xg + (size_t)r * KD + j * 8);
        }
        // first GEMM1 B slab (ch0, nh0, kb0)
        ld_slabB(bbuf[0], g_W1T, KD, tid);
        CP_COMMIT();
    }
    // biases + gates
    for (int i = tid; i < N1; i += THREADS) b1s[i] = b1[i];
    for (int i = tid; i < 128 * NE; i += THREADS) {
        int cc = i >> 3, e = i & 7;
        b2s[i] = (cc < NC) ? b2[(size_t)e * NC + cc] : 0.0f;
        gs[i]  = g_G[(size_t)(bm0 + cc) * NE + e];
    }
    CP_WAIT0();
    __syncthreads();

    // per-lane ldmatrix address offsets (bytes)
    const uint32_t aoff_x = (uint32_t)((m0w + (lane & 15)) * (X_ST * 2) + (lane >> 4) * 16);
    const uint32_t aoff_h = (uint32_t)((m0w + (lane & 15)) * (H_ST * 2) + (lane >> 4) * 16);
    const uint32_t boff   = (uint32_t)((n0w + ((lane >> 4) << 3) + (lane & 7)) * (B_ST * 2)
                                       + ((lane >> 3) & 1) * 16);

    float acc2[2][4][4];
    #pragma unroll
    for (int i = 0; i < 2; i++)
        #pragma unroll
        for (int j = 0; j < 4; j++)
            #pragma unroll
            for (int q = 0; q < 4; q++) acc2[i][j][q] = 0.0f;

    bool first = true;
    #pragma unroll 1
    for (int ch = 0; ch < NE; ch++) {
        #pragma unroll 1
        for (int nh = 0; nh < 2; nh++) {
            // ================= GEMM1: H-half = X @ W1T^T  (K=512) ==========
            const __half* W1b = g_W1T + (size_t)(ch * NH + nh * 128) * KD;
            if (!first) { ld_slabB(bbuf[0], W1b, KD, tid); CP_COMMIT(); }
            first = false;

            float acc1[2][4][4];
            #pragma unroll
            for (int i = 0; i < 2; i++)
                #pragma unroll
                for (int j = 0; j < 4; j++)
                    #pragma unroll
                    for (int q = 0; q < 4; q++) acc1[i][j][q] = 0.0f;

            #pragma unroll 1
            for (int kb = 0; kb < 8; kb++) {          // BK=64
                int cur = kb & 1;
                CP_WAIT0();
                __syncthreads();
                if (kb < 7) {
                    ld_slabB(bbuf[cur ^ 1], W1b + (kb + 1) * 64, KD, tid);
                    CP_COMMIT();
                }
                const uint32_t bc = bbuf[cur];
                #pragma unroll
                for (int kk = 0; kk < 4; kk++) {      // K=16 each
                    uint32_t afr[2][4], bfr[2][4];
                    #pragma unroll
                    for (int mf = 0; mf < 2; mf++)
                        ldm4(afr[mf], xs_u + aoff_x + (uint32_t)(mf * 16 * X_ST * 2
                                     + kb * 128 + kk * 32));
                    #pragma unroll
                    for (int nb = 0; nb < 2; nb++)
                        ldm4(bfr[nb], bc + boff + (uint32_t)(nb * 16 * B_ST * 2 + kk * 32));
                    #pragma unroll
                    for (int mf = 0; mf < 2; mf++)
                        #pragma unroll
                        for (int nf = 0; nf < 4; nf++)
                            mma_f16(acc1[mf][nf], afr[mf], &bfr[nf >> 1][(nf & 1) * 2]);
                }
            }

            // ---- epilogue 1: Hs = fp16(relu(acc1 + b1) * gate) ----
            #pragma unroll
            for (int mf = 0; mf < 2; mf++) {
                int r0 = m0w + mf * 16 + g;
                float g0 = gs[r0 * NE + ch];
                float g1 = gs[(r0 + 8) * NE + ch];
                #pragma unroll
                for (int nf = 0; nf < 4; nf++) {
                    int col = n0w + nf * 8 + 2 * t;
                    const float* bb = b1s + ch * NH + nh * 128 + col;
                    float v00 = fmaxf(acc1[mf][nf][0] + bb[0], 0.f) * g0;
                    float v01 = fmaxf(acc1[mf][nf][1] + bb[1], 0.f) * g0;
                    float v10 = fmaxf(acc1[mf][nf][2] + bb[0], 0.f) * g1;
                    float v11 = fmaxf(acc1[mf][nf][3] + bb[1], 0.f) * g1;
                    *reinterpret_cast<__half2*>(Hs + r0 * H_ST + col) =
                        __floats2half2_rn(v00, v01);
                    *reinterpret_cast<__half2*>(Hs + (r0 + 8) * H_ST + col) =
                        __floats2half2_rn(v10, v11);
                }
            }

            // ================= GEMM2: acc2 += H-half @ W2T^T  (K=128) ======
            const __half* W2b = g_W2T + ch * NH + nh * 128;
            ld_slabB(bbuf[0], W2b, N1, tid);
            CP_COMMIT();
            #pragma unroll 1
            for (int kb = 0; kb < 2; kb++) {
                int cur = kb & 1;
                CP_WAIT0();
                __syncthreads();
                if (kb < 1) {
                    ld_slabB(bbuf[1], W2b + 64, N1, tid);
                    CP_COMMIT();
                }
                const uint32_t bc = bbuf[cur];
                #pragma unroll
                for (int kk = 0; kk < 4; kk++) {
                    uint32_t afr[2][4], bfr[2][4];
                    #pragma unroll
                    for (int mf = 0; mf < 2; mf++)
                        ldm4(afr[mf], hs_u + aoff_h + (uint32_t)(mf * 16 * H_ST * 2
                                     + kb * 128 + kk * 32));
                    #pragma unroll
                    for (int nb = 0; nb < 2; nb++)
                        ldm4(bfr[nb], bc + boff + (uint32_t)(nb * 16 * B_ST * 2 + kk * 32));
                    #pragma unroll
                    for (int mf = 0; mf < 2; mf++)
                        #pragma unroll
                        for (int nf = 0; nf < 4; nf++)
                            mma_f16(acc2[mf][nf], afr[mf], &bfr[nf >> 1][(nf & 1) * 2]);
                }
            }
        }
    }

    // ================= final epilogue: out = acc2 + G @ b2 =================
    #pragma unroll
    for (int mf = 0; mf < 2; mf++) {
        int r0 = m0w + mf * 16 + g;
        #pragma unroll
        for (int nf = 0; nf < 4; nf++) {
            int col = n0w + nf * 8 + 2 * t;
            #pragma unroll
            for (int q = 0; q < 4; q++) {
                int r  = r0 + ((q >> 1) ? 8 : 0);
                int cc = col + (q & 1);
                if (cc < NC) {
                    float v = acc2[mf][nf][q];
                    const float* gv = gs  + r * NE;
                    const float* bv = b2s + cc * NE;
                    #pragma unroll
                    for (int e = 0; e < NE; e++) v += gv[e] * bv[e];
                    Out[(size_t)(bm0 + r) * NC + cc] = v;
                }
            }
        }
    }
}

// ---------------- launch ----------------
extern "C" void kernel_launch(void* const* d_in, const int* in_sizes, int n_in,
                              void* d_out, int out_size) {
    const float* x  = (const float*)d_in[0];
    const float* W1 = (const float*)d_in[1];
    const float* b1 = (const float*)d_in[2];
    const float* W2 = (const float*)d_in[3];
    const float* b2 = (const float*)d_in[4];
    const float* Wg = (const float*)d_in[5];
    const float* bg = (const float*)d_in[6];
    float* out = (float*)d_out;

    k_tw1  <<<dim3(NH / 32, KD / 32, NE), dim3(32, 8)>>>(W1);
    k_tw2  <<<(128 * N1) / 256, 256>>>(W2);
    k_gates<<<B_TOK / 8, 256>>>(x, Wg, bg);

    cudaFuncSetAttribute(k_moe, cudaFuncAttributeMaxDynamicSharedMemorySize, SM_TOT);
    k_moe<<<B_TOK / BM, THREADS, SM_TOT>>>(b1, b2, out);
}